// round 16
// baseline (speedup 1.0000x reference)
#include <cuda_runtime.h>
#include <math.h>

// Fixed-shape problem: N=16384, D=8, pid in [0,2000), K=128, R=1
#define NMAX    16384
#define NPIDMAX 2048
#define KSEL2   129     // top-(K+1) including self (self weight = 0)
#define CPT     4       // condensation points per repulsion block
#define RT      256     // threads per block
#define NB      256     // histogram bins over D2=256*d2
#define BCAP    128     // boundary-bin candidate capacity per CP

// -------- device scratch (small, allocation-free) --------
__device__ unsigned long long g_best[NPIDMAX];
__device__ float  g_q[NMAX];
__device__ float4 g_pack[NMAX * 3];   // {x0..3},{x4..7},{n2,q,pid,0}
__device__ int    g_cplist[NPIDMAX];
__device__ int    g_cpcount;
__device__ double g_att;
__device__ double g_rep;
__device__ int    g_maskcnt;

// predicated shared histogram increment (R9-proven light form)
__device__ __forceinline__ void hist_add(unsigned smem_addr, float D2) {
    asm volatile(
        "{\n\t.reg .pred p;\n\t"
        "setp.le.f32 p, %1, 0f43800000;\n\t"   // D2 <= 256.0f
        "@p red.shared.add.u32 [%0], 1;\n\t}"
        :: "r"(smem_addr), "f"(D2) : "memory");
}

__global__ void k_init() {
    int i = blockIdx.x * blockDim.x + threadIdx.x;
    if (i < NPIDMAX) g_best[i] = 0ULL;
    if (i == 0) { g_cpcount = 0; g_att = 0.0; g_rep = 0.0; g_maskcnt = 0; }
}

__global__ void k_bestq(const float* __restrict__ beta, const int* __restrict__ pid,
                        const float* __restrict__ x, int N) {
    int i = blockIdx.x * blockDim.x + threadIdx.x;
    if (i >= N) return;
    float b = beta[i];
    float t = atanhf(b);
    float q = t * t + 0.01f;
    g_q[i] = q;
    float4 v0 = *(const float4*)(x + (size_t)i * 8);
    float4 v1 = *(const float4*)(x + (size_t)i * 8 + 4);
    float n2 = v0.x * v0.x + v0.y * v0.y + v0.z * v0.z + v0.w * v0.w
             + v1.x * v1.x + v1.y * v1.y + v1.z * v1.z + v1.w * v1.w;
    int p = pid[i];
    g_pack[3 * i + 0] = v0;
    g_pack[3 * i + 1] = v1;
    g_pack[3 * i + 2] = make_float4(n2, q, __int_as_float(p), 0.0f);
    if (p > 0 && p < NPIDMAX) {
        unsigned long long key =
            ((unsigned long long)__float_as_uint(b) << 32) |
            (unsigned long long)(0xFFFFFFFFu - (unsigned)i);
        atomicMax(&g_best[p], key);
    }
}

__global__ void k_attract(const float* __restrict__ x, const int* __restrict__ pid,
                          const int* __restrict__ recon, const float* __restrict__ pt,
                          const float* __restrict__ eta, int N) {
    int i = blockIdx.x * blockDim.x + threadIdx.x;
    if (i > 0 && i < NPIDMAX) {
        unsigned long long key = g_best[i];
        if (key != 0ULL) {
            int idx = (int)(0xFFFFFFFFu - (unsigned)(key & 0xFFFFFFFFull));
            int pos = atomicAdd(&g_cpcount, 1);
            g_cplist[pos] = idx;
        }
    }
    float va = 0.0f; int m = 0;
    if (i < N) {
        int p = pid[i];
        if (p > 0 && pt[i] > 0.9f && recon[i] > 0 && fabsf(eta[i]) < 4.0f) {
            unsigned long long key = g_best[p];
            int a = (int)(0xFFFFFFFFu - (unsigned)(key & 0xFFFFFFFFull));
            const float4* xi = (const float4*)(x + (size_t)i * 8);
            const float4* xa = (const float4*)(x + (size_t)a * 8);
            float4 i0 = xi[0], i1 = xi[1], a0 = xa[0], a1 = xa[1];
            float d, d2 = 0.0f;
            d = i0.x - a0.x; d2 += d * d;
            d = i0.y - a0.y; d2 += d * d;
            d = i0.z - a0.z; d2 += d * d;
            d = i0.w - a0.w; d2 += d * d;
            d = i1.x - a1.x; d2 += d * d;
            d = i1.y - a1.y; d2 += d * d;
            d = i1.z - a1.z; d2 += d * d;
            d = i1.w - a1.w; d2 += d * d;
            va = d2 * g_q[i] * g_q[a];
            m = 1;
        }
    }
    #pragma unroll
    for (int o = 16; o; o >>= 1) {
        va += __shfl_down_sync(0xFFFFFFFFu, va, o);
        m  += __shfl_down_sync(0xFFFFFFFFu, m,  o);
    }
    if ((threadIdx.x & 31) == 0 && (m || va != 0.0f)) {
        atomicAdd(&g_att, (double)va);
        atomicAdd(&g_maskcnt, m);
    }
}

// scaled distance chain: D2 = 256*d2 (m2x = -512*xc, n2cs = 256*|xc|^2)
// identical expression in both passes -> bit-identical classification
#define D2_CHAIN(res, V0, V1, N2J, c)                 \
    float res = fmaf(V0.x, m2x[c][0], n2cs[c]);       \
    res = fmaf(V0.y, m2x[c][1], res);                 \
    res = fmaf(V0.z, m2x[c][2], res);                 \
    res = fmaf(V0.w, m2x[c][3], res);                 \
    res = fmaf(V1.x, m2x[c][4], res);                 \
    res = fmaf(V1.y, m2x[c][5], res);                 \
    res = fmaf(V1.z, m2x[c][6], res);                 \
    res = fmaf(V1.w, m2x[c][7], res);                 \
    res = fmaf(N2J, 256.0f, res);

// ---- repulsion: R15 structure; launch_bounds(256,3) to eliminate spills ----
__global__ void __launch_bounds__(RT, 3) k_repulse(int N) {
    __shared__ int      s_hist[CPT][NB];
    __shared__ int      s_Bs[CPT];
    __shared__ int      s_rs[CPT];
    __shared__ int      s_bcnt[CPT];
    __shared__ unsigned s_bk[CPT][BCAP];
    __shared__ float    s_bw[CPT][BCAP];
    __shared__ float    s_qc[CPT];
    __shared__ float    s_red[RT / 32];

    int tid   = threadIdx.x;
    int ncp   = g_cpcount;
    int cbase = blockIdx.x * CPT;
    if (cbase >= ncp) return;

    float m2x[CPT][8], n2cs[CPT];
    int   pidc[CPT];
    #pragma unroll
    for (int c = 0; c < CPT; c++) {
        int slot = cbase + c;
        bool act = slot < ncp;
        int ci = act ? g_cplist[slot] : 0;
        float4 p0 = g_pack[3 * ci + 0];
        float4 p1 = g_pack[3 * ci + 1];
        float4 p2 = g_pack[3 * ci + 2];
        m2x[c][0] = -512.0f * p0.x; m2x[c][1] = -512.0f * p0.y;
        m2x[c][2] = -512.0f * p0.z; m2x[c][3] = -512.0f * p0.w;
        m2x[c][4] = -512.0f * p1.x; m2x[c][5] = -512.0f * p1.y;
        m2x[c][6] = -512.0f * p1.z; m2x[c][7] = -512.0f * p1.w;
        n2cs[c] = act ? 256.0f * p2.x : 1e30f;
        pidc[c] = act ? __float_as_int(p2.z) : -1;
        if (tid == 0) s_qc[c] = act ? p2.y : 0.0f;
    }

    for (int h = tid; h < CPT * NB; h += RT) ((int*)s_hist)[h] = 0;
    if (tid < CPT) s_bcnt[tid] = 0;
    __syncthreads();

    unsigned histbase[CPT];
    #pragma unroll
    for (int c = 0; c < CPT; c++)
        histbase[c] = (unsigned)__cvta_generic_to_shared(&s_hist[c][0]);

    // ---- Pass A: branchless count histogram ----
    for (int j = tid; j < N; j += RT) {
        float4 v0 = g_pack[3 * j + 0];
        float4 v1 = g_pack[3 * j + 1];
        float4 v2 = g_pack[3 * j + 2];
        float n2j = v2.x;
        #pragma unroll
        for (int c = 0; c < CPT; c++) {
            D2_CHAIN(D2, v0, v1, n2j, c)
            int bb = min((int)fmaxf(D2, 0.0f), NB - 1);
            hist_add(histbase[c] + (unsigned)(bb << 2), D2);
        }
    }
    __syncthreads();

    // ---- selection: boundary bin B and residual r per CP ----
    if (tid < CPT) {
        int cum = 0, B = NB, r = 0;
        for (int b = 0; b < NB; b++) {
            int nc = cum + s_hist[tid][b];
            if (nc >= KSEL2) { B = b; r = KSEL2 - cum; break; }
            cum = nc;
        }
        s_Bs[tid] = B; s_rs[tid] = r;
    }
    __syncthreads();

    float Bf[CPT]; int Breg[CPT];
    #pragma unroll
    for (int c = 0; c < CPT; c++) { Breg[c] = s_Bs[c]; Bf[c] = (float)s_Bs[c]; }

    // ---- Pass B: float-compare classification; predicated accumulate ----
    float acc[CPT];
    #pragma unroll
    for (int c = 0; c < CPT; c++) acc[c] = 0.0f;

    for (int j = tid; j < N; j += RT) {
        float4 v0 = g_pack[3 * j + 0];
        float4 v1 = g_pack[3 * j + 1];
        float4 v2 = g_pack[3 * j + 2];
        float n2j = v2.x;
        float qj  = v2.y;
        int   pj  = __float_as_int(v2.z);
        bool anyB = false;
        float ds[CPT];
        #pragma unroll
        for (int c = 0; c < CPT; c++) {
            D2_CHAIN(D2, v0, v1, n2j, c)
            ds[c] = D2;
            float w = fmaf(-0.0625f, sqrtf(fmaxf(D2, 0.0f)), 1.0f) * qj;
            bool sel = (D2 < Bf[c]) && (pj != pidc[c]);
            acc[c] += sel ? w : 0.0f;
            anyB |= (D2 >= Bf[c]) && (D2 <= 256.0f);
        }
        if (__any_sync(0xFFFFFFFFu, anyB)) {
            #pragma unroll
            for (int c = 0; c < CPT; c++) {
                float D2 = ds[c];
                if (D2 >= Bf[c] && D2 <= 256.0f) {
                    float Dc = fmaxf(D2, 0.0f);
                    int bb = min((int)Dc, NB - 1);       // exact bin, cold path
                    if (bb == Breg[c]) {
                        float w = (pj != pidc[c])
                                  ? fmaf(-0.0625f, sqrtf(Dc), 1.0f) * qj : 0.0f;
                        int p = atomicAdd(&s_bcnt[c], 1);
                        if (p < BCAP) { s_bk[c][p] = __float_as_uint(Dc); s_bw[c][p] = w; }
                    }
                }
            }
        }
    }
    __syncthreads();

    // ---- boundary mini-rank + per-CP reduction ----
    #pragma unroll
    for (int c = 0; c < CPT; c++) {
        float part = acc[c];
        int m = min(s_bcnt[c], BCAP);
        int r = s_rs[c];
        if (r > 0) {
            for (int e = tid; e < m; e += RT) {
                unsigned ke = s_bk[c][e];
                int rank = 0;
                for (int k = 0; k < m; k++) {
                    unsigned kk = s_bk[c][k];
                    rank += (kk < ke) || (kk == ke && k < e);
                }
                if (rank < r) part += s_bw[c][e];
            }
        }
        #pragma unroll
        for (int o = 16; o; o >>= 1) part += __shfl_down_sync(0xFFFFFFFFu, part, o);
        if ((tid & 31) == 0) s_red[tid >> 5] = part;
        __syncthreads();
        if (tid == 0) {
            float tot = 0.0f;
            #pragma unroll
            for (int w = 0; w < RT / 32; w++) tot += s_red[w];
            if (tot != 0.0f) atomicAdd(&g_rep, (double)(tot * s_qc[c]));
        }
        __syncthreads();
    }
}

__global__ void k_final(float* out, int N) {
    if (blockIdx.x == 0 && threadIdx.x == 0) {
        int mc = g_maskcnt;
        out[0] = (float)(mc > 0 ? g_att / (double)mc : 0.0);
        out[1] = (float)(g_rep / (double)N);
        out[2] = 0.0f;
        out[3] = 0.0f;
    }
}

extern "C" void kernel_launch(void* const* d_in, const int* in_sizes, int n_in,
                              void* d_out, int out_size) {
    const float* beta  = (const float*)d_in[0];
    const float* x     = (const float*)d_in[1];
    const int*   pid   = (const int*)d_in[2];
    const int*   recon = (const int*)d_in[3];
    const float* pt    = (const float*)d_in[4];
    const float* eta   = (const float*)d_in[5];
    float* out = (float*)d_out;
    int N = in_sizes[0];

    k_init<<<(NPIDMAX + 255) / 256, 256>>>();
    k_bestq<<<(N + 255) / 256, 256>>>(beta, pid, x, N);
    k_attract<<<(N + 127) / 128, 128>>>(x, pid, recon, pt, eta, N);
    int ngrp = (NPIDMAX + CPT - 1) / CPT;   // 512 blocks
    k_repulse<<<ngrp, RT>>>(N);
    k_final<<<1, 32>>>(out, N);
}